// round 9
// baseline (speedup 1.0000x reference)
#include <cuda_runtime.h>
#include <cstdint>

// ============================================================================
// Problem shapes (fixed by reference setup_inputs)
// ============================================================================
#define BATCH      4
#define NPTS       8192
#define L_DIFF     98304       // 4*8192*3
#define L_STYLE    2048        // 4*512
#define L_CONTENT  1048576     // 4*1024*256
#define L_ID       98304

// bucketing
#define NB         256
#define XMIN       (-5.12f)
#define BW         0.04f
#define INV_BW     25.0f

// kernel 1: 8 build blocks + 64 MSE blocks
#define K1_THREADS 256
#define BUILD_BLKS 8
#define MSE_BLKS   64
#define K1_BLOCKS  (BUILD_BLKS + MSE_BLKS)

// kernel 2: 256 query blocks (2 dir * 4 batch * 32 chunks of 256 queries)
#define K2_THREADS 256
#define K2_BLOCKS  256

// ============================================================================
// Scratch (device globals; no allocation allowed).
// g_sorted / g_bstart are fully overwritten every call by kernel 1.
// g_acc / g_cham / g_ctr: zero-init == clean state; kernel 2's final block
// resets them each call -> deterministic replays, no init launch.
// ============================================================================
__device__ float4 g_sorted[8][NPTS];    // [cloud*4+b]; cloud 0 = x_original, 1 = x_cycle
__device__ int    g_bstart[8][NB + 1];  // bucket prefix offsets
__device__ double g_acc[4];             // diff, style, content, identity sums
__device__ double g_cham;               // sum of sqrt(min d2) over all 65536 queries
__device__ unsigned int g_ctr;          // last-block ticket (auto-wrap)

static __device__ __forceinline__ int bucket_of(float x) {
    int k = (int)((x - XMIN) * INV_BW);
    return k < 0 ? 0 : (k > NB - 1 ? NB - 1 : k);
}

// ============================================================================
// Kernel 1, blocks [0,8): bucket-sort one cloud (by x) into g_sorted + prefix.
// Order within a bucket is atomic-order (nondeterministic) — harmless: all
// consumers reduce with min / mean, which are order-independent in value
// (up to ~1e-7 float jitter, far inside the 1e-3 threshold).
// ============================================================================
static __device__ __forceinline__ void build_cloud(
    int id, const float* __restrict__ xo, const float* __restrict__ xc,
    int* hist, int* pos) {

    const int cloud = id >> 2;
    const int b     = id & 3;
    const float* src = (cloud ? xc : xo) + (size_t)b * NPTS * 3;
    const int t = threadIdx.x;

    for (int k = t; k < NB; k += K1_THREADS) hist[k] = 0;
    __syncthreads();

    for (int i = t; i < NPTS; i += K1_THREADS)
        atomicAdd(&hist[bucket_of(src[3 * i])], 1);
    __syncthreads();

    if (t == 0) {
        int run = 0;
        for (int k = 0; k < NB; k++) {
            pos[k] = run;
            g_bstart[id][k] = run;
            run += hist[k];
        }
        g_bstart[id][NB] = run;   // == NPTS
    }
    __syncthreads();

    for (int i = t; i < NPTS; i += K1_THREADS) {
        float x = src[3 * i], y = src[3 * i + 1], z = src[3 * i + 2];
        int k = bucket_of(x);
        int p = atomicAdd(&pos[k], 1);
        g_sorted[id][p] = make_float4(x, y, z, 0.0f);
    }
}

// ============================================================================
// Kernel 1, blocks [8,72): all 4 MSE sums, float4-vectorized -> g_acc.
// ============================================================================
static __device__ __forceinline__ float mse_part_v4(const float4* __restrict__ a,
                                                    const float4* __restrict__ b,
                                                    int n4, int gid, int stride) {
    float s = 0.f;
    for (int i = gid; i < n4; i += stride) {
        float4 va = a[i], vb = b[i];
        float d0 = va.x - vb.x, d1 = va.y - vb.y, d2 = va.z - vb.z, d3 = va.w - vb.w;
        s += d0 * d0 + d1 * d1 + d2 * d2 + d3 * d3;
    }
    return s;
}

static __device__ __forceinline__ void mse_part(
    int m, const float* pred, const float* targ, const float* ssim,
    const float* sreal, const float* corg, const float* cgen,
    const float* xorg, const float* xid, float* sm) {

    const int gid    = m * K1_THREADS + threadIdx.x;
    const int stride = MSE_BLKS * K1_THREADS;

    float s[4];
    s[0] = mse_part_v4((const float4*)pred, (const float4*)targ,  L_DIFF / 4,    gid, stride);
    s[1] = mse_part_v4((const float4*)ssim, (const float4*)sreal, L_STYLE / 4,   gid, stride);
    s[2] = mse_part_v4((const float4*)corg, (const float4*)cgen,  L_CONTENT / 4, gid, stride);
    s[3] = mse_part_v4((const float4*)xorg, (const float4*)xid,   L_ID / 4,      gid, stride);

    if (threadIdx.x < 4) sm[threadIdx.x] = 0.f;
    __syncthreads();
#pragma unroll
    for (int k = 0; k < 4; k++) {
#pragma unroll
        for (int off = 16; off > 0; off >>= 1)
            s[k] += __shfl_down_sync(0xFFFFFFFFu, s[k], off);
        if ((threadIdx.x & 31) == 0) atomicAdd(&sm[k], s[k]);
    }
    __syncthreads();
    if (threadIdx.x < 4) atomicAdd(&g_acc[threadIdx.x], (double)sm[threadIdx.x]);
}

__global__ void __launch_bounds__(K1_THREADS)
build_mse_kernel(const float* __restrict__ xo,   const float* __restrict__ xc,
                 const float* __restrict__ pred, const float* __restrict__ targ,
                 const float* __restrict__ ssim, const float* __restrict__ sreal,
                 const float* __restrict__ corg, const float* __restrict__ cgen,
                 const float* __restrict__ xid) {
    __shared__ int   hist[NB];
    __shared__ int   pos[NB];
    __shared__ float sm[4];
    const int bid = blockIdx.x;
    if (bid < BUILD_BLKS) {
        build_cloud(bid, xo, xc, hist, pos);
    } else {
        mse_part(bid - BUILD_BLKS, pred, targ, ssim, sreal, corg, cgen, xo, xid, sm);
    }
}

// ============================================================================
// Kernel 2: windowed exact nearest-neighbor queries.
// Each warp takes 32 consecutive SORTED queries (similar x) -> candidate
// buckets are warp-uniform: broadcast loads, vote-driven uniform expansion.
// Exactness: bucket [k] only skipped when (edge distance)^2 >= current best
// for ALL lanes; edge distance <= true |dx| <= true distance (eps-padded
// against float edge rounding), so the true argmin is never skipped.
// ============================================================================
__global__ void __launch_bounds__(K2_THREADS)
query_kernel(float* __restrict__ out, int out_size) {
    const int qid   = blockIdx.x;         // 0..255
    const int dir   = qid >> 7;           // 0: queries=xo, cands=xc ; 1: swapped
    const int b     = (qid >> 5) & 3;
    const int chunk = qid & 31;
    const int qc = dir ? 1 : 0;
    const int cc = 1 - qc;

    const float4* __restrict__ Q   = g_sorted[qc * 4 + b] + chunk * K2_THREADS;
    const float4* __restrict__ C   = g_sorted[cc * 4 + b];
    const int*    __restrict__ bst = g_bstart[cc * 4 + b];

    const int lane = threadIdx.x & 31;
    const int wid  = threadIdx.x >> 5;
    const unsigned FULL = 0xFFFFFFFFu;

    float4 q = Q[wid * 32 + lane];
    float best = 3.4e38f;

    int myb = bucket_of(q.x);
    int l = __shfl_sync(FULL, myb, 0);    // sorted ascending -> lane0 lowest
    int r = __shfl_sync(FULL, myb, 31);

    // scan a bucket (warp-uniform range; candidate loads broadcast)
    auto scan = [&](int k) {
        int s = bst[k], e = bst[k + 1];
        for (int i = s; i < e; i++) {
            float4 c = C[i];
            float dx = q.x - c.x, dy = q.y - c.y, dz = q.z - c.z;
            float d2 = fmaf(dx, dx, fmaf(dy, dy, dz * dz));
            best = fminf(best, d2);
        }
    };

    for (int k = l; k <= r; k++) scan(k);

    while (true) {
        // right edge of bucket l-1 is XMIN + l*BW; left edge of r+1 is XMIN+(r+1)*BW
        float dl = q.x - (XMIN + l * BW);
        float dr = (XMIN + (r + 1) * BW) - q.x;
        dl = fmaxf(dl - 1e-4f, 0.0f);     // eps pad: bound stays an underestimate
        dr = fmaxf(dr - 1e-4f, 0.0f);
        unsigned vl = __ballot_sync(FULL, dl * dl < best);
        unsigned vr = __ballot_sync(FULL, dr * dr < best);
        bool aL = (l > 0)      && (vl != 0u);
        bool aR = (r < NB - 1) && (vr != 0u);
        if (!aL && !aR) break;
        if (aL) { l--; scan(l); }
        if (aR) { r++; scan(r); }
    }

    float contrib = sqrtf(best);          // best >= 0 by construction

    // block reduction -> g_cham
    __shared__ float warpsum[K2_THREADS / 32];
    __shared__ bool  s_last;
#pragma unroll
    for (int off = 16; off > 0; off >>= 1)
        contrib += __shfl_down_sync(FULL, contrib, off);
    if (lane == 0) warpsum[wid] = contrib;
    __syncthreads();
    if (wid == 0) {
        float v = (lane < K2_THREADS / 32) ? warpsum[lane] : 0.f;
#pragma unroll
        for (int off = 4; off > 0; off >>= 1)
            v += __shfl_down_sync(FULL, v, off);
        if (lane == 0) atomicAdd(&g_cham, (double)v);
    }

    // last-block combine + state reset
    __threadfence();
    if (threadIdx.x == 0) {
        unsigned t = atomicInc(&g_ctr, gridDim.x - 1);  // wraps to 0
        s_last = (t == gridDim.x - 1);
    }
    __syncthreads();
    if (s_last && threadIdx.x == 0) {
        double diff     = g_acc[0] / (double)L_DIFF;
        double stylemse = g_acc[1] / (double)L_STYLE;
        double content  = g_acc[2] / (double)L_CONTENT;
        double identity = g_acc[3] / (double)L_ID;
        double cycle    = g_cham / (double)(BATCH * NPTS * 2);
        double style    = -stylemse;
        double tot = diff + 0.5 * style + 0.5 * content + cycle + 0.5 * identity;
        if (out_size > 0) out[0] = (float)diff;
        if (out_size > 1) out[1] = (float)style;
        if (out_size > 2) out[2] = (float)content;
        if (out_size > 3) out[3] = (float)cycle;
        if (out_size > 4) out[4] = (float)identity;
        if (out_size > 5) out[5] = (float)tot;
        for (int i = 6; i < out_size; i++) out[i] = 0.f;
        g_acc[0] = 0.0; g_acc[1] = 0.0; g_acc[2] = 0.0; g_acc[3] = 0.0;
        g_cham = 0.0;
    }
}

// ============================================================================
// Launch (graph-capturable). Inputs:
// 0 pred_noise, 1 target_noise, 2 style_sim, 3 style_real,
// 4 content_original, 5 content_generated, 6 x_cycle, 7 x_original, 8 x_identity
// ============================================================================
extern "C" void kernel_launch(void* const* d_in, const int* in_sizes, int n_in,
                              void* d_out, int out_size) {
    (void)n_in; (void)in_sizes;
    const float* pred  = (const float*)d_in[0];
    const float* targ  = (const float*)d_in[1];
    const float* ssim  = (const float*)d_in[2];
    const float* sreal = (const float*)d_in[3];
    const float* corg  = (const float*)d_in[4];
    const float* cgen  = (const float*)d_in[5];
    const float* xcyc  = (const float*)d_in[6];
    const float* xorg  = (const float*)d_in[7];
    const float* xid   = (const float*)d_in[8];
    float* out = (float*)d_out;

    build_mse_kernel<<<K1_BLOCKS, K1_THREADS>>>(xorg, xcyc, pred, targ,
                                                ssim, sreal, corg, cgen, xid);

    query_kernel<<<K2_BLOCKS, K2_THREADS>>>(out, out_size);
}